// round 2
// baseline (speedup 1.0000x reference)
#include <cuda_runtime.h>
#include <math.h>

#define DD 1024
#define HH 256
#define KK 64
#define BB 64
#define TT 2048
#define H2 512

// ---- scratch (no allocations allowed; __device__ globals) ----
__device__ float g_action[BB * DD];   // mean over T of x  (atomic accum)
__device__ float g_ctx[DD];           // mean of context buffer
__device__ float g_h1pre[HH];         // ctx @ ce_w1 (pre-bias/gelu, atomic)
__device__ float g_epre[DD];          // gelu(h1) @ ce_w2 (pre-bias)
__device__ float g_ctx_enc[DD];       // rmsnorm output
__device__ float g_nsh[HH];           // ctx_enc @ ns_w1 (atomic)
__device__ float g_norm_w[KK];        // softmax weights (batch-invariant)
__device__ float g_basec[H2];         // ctx_enc @ wc (atomic)
__device__ float g_svctx[HH];         // ctx_enc @ sv_w1[:1024] (atomic)
__device__ float g_proto_t[KK * H2];  // prototypes @ wp
__device__ float g_act_t[BB * H2];    // action @ wa
__device__ float g_svh[BB * HH];      // action @ sv_w1[1024:]

__device__ __forceinline__ float gelu_f(float x) {
    return 0.5f * x * (1.0f + erff(x * 0.70710678118654752440f));
}
__device__ __forceinline__ float sigmoid_f(float x) {
    return 1.0f / (1.0f + expf(-x));
}

// ---- zero the atomic accumulators ----
__global__ void k_init() {
    int idx = blockIdx.x * 1024 + threadIdx.x;
    if (idx < BB * DD) g_action[idx] = 0.0f;
    if (blockIdx.x == 0) {
        int t = threadIdx.x;
        if (t < HH) { g_h1pre[t] = 0.0f; g_nsh[t] = 0.0f; g_svctx[t] = 0.0f; }
        if (t < H2) g_basec[t] = 0.0f;
    }
}

// ---- big reduction: action[b][d] = mean_t x[b][t][d] ----
// grid (64, 32), block 256. Each block: one batch, 64 t-rows, full D via float4.
__global__ void k_reduce(const float* __restrict__ x) {
    int b = blockIdx.x;
    int tc = blockIdx.y;
    int tid = threadIdx.x;
    const float4* xp = reinterpret_cast<const float4*>(x)
                     + ((size_t)b * TT + (size_t)tc * 64) * 256 + tid;
    float4 acc = make_float4(0.f, 0.f, 0.f, 0.f);
#pragma unroll 8
    for (int t = 0; t < 64; t++) {
        float4 v = xp[(size_t)t * 256];
        acc.x += v.x; acc.y += v.y; acc.z += v.z; acc.w += v.w;
    }
    const float s = 1.0f / 2048.0f;
    float* o = g_action + b * DD + tid * 4;
    atomicAdd(o + 0, acc.x * s);
    atomicAdd(o + 1, acc.y * s);
    atomicAdd(o + 2, acc.z * s);
    atomicAdd(o + 3, acc.w * s);
}

// ---- ctx = mean over 16 rows of context buffer ----
__global__ void k_ctx_mean(const float* __restrict__ cb) {
    int tid = threadIdx.x;
    for (int i = 0; i < 4; i++) {
        int d = tid + i * 256;
        float a = 0.f;
#pragma unroll
        for (int r = 0; r < 16; r++) a += cb[r * DD + d];
        g_ctx[d] = a * (1.0f / 16.0f);
    }
}

// ---- partial-d GEMV with atomic accumulate: out[j] += sum_{d in chunk} v[d]*W[d*N+j]
// grid = 8 (chunks of 128 d), blockDim = N (256 or 512)
__global__ void k_gemv_atomic(const float* __restrict__ W, int vsel, int osel, int N) {
    __shared__ float vs[128];
    const float* v = (vsel == 0) ? g_ctx : g_ctx_enc;
    float* outAcc = (osel == 0) ? g_h1pre : (osel == 1) ? g_nsh
                  : (osel == 2) ? g_basec : g_svctx;
    int d0 = blockIdx.x * 128;
    int tid = threadIdx.x;
    if (tid < 128) vs[tid] = v[d0 + tid];
    __syncthreads();
    float acc = 0.f;
    const float* Wp = W + (size_t)d0 * N + tid;
#pragma unroll 8
    for (int i = 0; i < 128; i++) acc += vs[i] * Wp[(size_t)i * N];
    atomicAdd(&outAcc[tid], acc);
}

// ---- e_pre[d] = sum_j gelu(h1pre[j]+ce_b1[j]) * ce_w2[j][d] ; grid 4, block 256 ----
__global__ void k_epre(const float* __restrict__ ce_w2, const float* __restrict__ ce_b1) {
    __shared__ float hs[HH];
    int tid = threadIdx.x;
    hs[tid] = gelu_f(g_h1pre[tid] + ce_b1[tid]);
    __syncthreads();
    int d = blockIdx.x * 256 + tid;
    float acc = 0.f;
#pragma unroll 8
    for (int j = 0; j < HH; j++) acc += hs[j] * ce_w2[(size_t)j * DD + d];
    g_epre[d] = acc;
}

// ---- rmsnorm: ctx_enc = e * rsqrt(mean(e^2)+eps) * rms_w ; 1 block 256 thr ----
__global__ void k_rms(const float* __restrict__ ce_b2, const float* __restrict__ rms_w) {
    __shared__ float red[256];
    int tid = threadIdx.x;
    float e[4];
    float ss = 0.f;
#pragma unroll
    for (int i = 0; i < 4; i++) {
        int d = tid + i * 256;
        e[i] = g_epre[d] + ce_b2[d];
        ss += e[i] * e[i];
    }
    red[tid] = ss;
    __syncthreads();
    for (int s = 128; s > 0; s >>= 1) {
        if (tid < s) red[tid] += red[tid + s];
        __syncthreads();
    }
    float inv = rsqrtf(red[0] * (1.0f / 1024.0f) + 1e-6f);
#pragma unroll
    for (int i = 0; i < 4; i++) {
        int d = tid + i * 256;
        g_ctx_enc[d] = e[i] * inv * rms_w[d];
    }
}

// ---- norm_weights: softmax over K of gelu(nsh+b1) @ ns_w2 + ns_b2 ; 1 block 256 thr ----
__global__ void k_norm_weights(const float* __restrict__ ns_b1,
                               const float* __restrict__ ns_w2,
                               const float* __restrict__ ns_b2) {
    __shared__ float ts[HH];
    __shared__ float lg[KK];
    int tid = threadIdx.x;
    ts[tid] = gelu_f(g_nsh[tid] + ns_b1[tid]);
    __syncthreads();
    if (tid < KK) {
        float a = ns_b2[tid];
#pragma unroll 8
        for (int j = 0; j < HH; j++) a += ts[j] * ns_w2[j * KK + tid];
        lg[tid] = a;
    }
    __syncthreads();
    if (tid < KK) {
        float m = -1e30f;
        for (int k = 0; k < KK; k++) m = fmaxf(m, lg[k]);
        float s = 0.f;
        for (int k = 0; k < KK; k++) s += expf(lg[k] - m);
        g_norm_w[tid] = expf(lg[tid] - m) / s;
    }
}

// ---- skinny GEMM: C[64 x N] = A[64 x 1024] @ W[1024 x N]
// grid (8 m-tiles, N/64 n-tiles), block 256. Shared A tile 8x1024 (32KB).
__global__ void k_gemm(const float* __restrict__ Aext, const float* __restrict__ W,
                       int asel, int csel, int N) {
    __shared__ float As[8 * DD];
    const float* A = asel ? g_action : Aext;
    float* C = (csel == 0) ? g_proto_t : (csel == 1) ? g_act_t : g_svh;
    int tid = threadIdx.x;
    int mbase = blockIdx.x * 8;
    const float* Ap = A + (size_t)mbase * DD;
    for (int i = tid; i < 8 * DD; i += 256) As[i] = Ap[i];
    __syncthreads();
    int h = tid & 63;
    int g = tid >> 6;          // 4 groups x 2 rows each
    int n = blockIdx.y * 64 + h;
    const float* Wp = W + n;
    const float* a0 = As + (g * 2) * DD;
    const float* a1 = a0 + DD;
    float acc0 = 0.f, acc1 = 0.f;
#pragma unroll 4
    for (int d = 0; d < DD; d++) {
        float w = Wp[(size_t)d * N];
        acc0 += a0[d] * w;
        acc1 += a1[d] * w;
    }
    C[(size_t)(mbase + g * 2) * N + n] = acc0;
    C[(size_t)(mbase + g * 2 + 1) * N + n] = acc1;
}

// ---- conformance + weighted_conf + violation ; grid 64 (per batch), block 256 ----
__global__ void k_conf(const float* __restrict__ nm_b1, const float* __restrict__ nm_w2,
                       const float* __restrict__ nm_b2, float* __restrict__ out) {
    int b = blockIdx.x;
    int tid = threadIdx.x;
    __shared__ float s[H2];
    __shared__ float w2[H2];
    __shared__ float conf[KK];
    for (int i = tid; i < H2; i += 256) {
        s[i] = g_basec[i] + nm_b1[i] + g_act_t[b * H2 + i];
        w2[i] = nm_w2[i];
    }
    __syncthreads();
    int warp = tid >> 5, lane = tid & 31;
    float bias2 = nm_b2[0];
    for (int kk = 0; kk < 8; kk++) {
        int k = warp * 8 + kk;
        const float* pp = g_proto_t + k * H2;
        float acc = 0.f;
        for (int h = lane; h < H2; h += 32)
            acc += gelu_f(s[h] + pp[h]) * w2[h];
        for (int o = 16; o > 0; o >>= 1)
            acc += __shfl_down_sync(0xffffffffu, acc, o);
        if (lane == 0) conf[k] = sigmoid_f(acc + bias2);
    }
    __syncthreads();
    if (tid == 0) {
        float wc = 0.f;
        for (int k = 0; k < KK; k++) wc += conf[k] * g_norm_w[k];
        out[64 + b] = wc;          // weighted_conf
        out[128 + b] = 1.0f - wc;  // violation
    }
}

// ---- severity + norm_penalty ; grid 64, block 256 ----
__global__ void k_sev(const float* __restrict__ sv_b1, const float* __restrict__ sv_w2,
                      const float* __restrict__ sv_b2, float* __restrict__ out) {
    int b = blockIdx.x;
    int tid = threadIdx.x;
    __shared__ float red[256];
    float v = gelu_f(g_svh[b * HH + tid] + g_svctx[tid] + sv_b1[tid]) * sv_w2[tid];
    red[tid] = v;
    __syncthreads();
    for (int s = 128; s > 0; s >>= 1) {
        if (tid < s) red[tid] += red[tid + s];
        __syncthreads();
    }
    if (tid == 0) {
        float sev = sigmoid_f(red[0] + sv_b2[0]);
        float viol = out[128 + b];
        out[192 + b] = sev;                 // severity
        out[b] = viol * sev * 0.1f;         // norm_penalty (alpha=0.1)
    }
}

extern "C" void kernel_launch(void* const* d_in, const int* in_sizes, int n_in,
                              void* d_out, int out_size) {
    const float* x      = (const float*)d_in[0];
    const float* cb     = (const float*)d_in[1];
    const float* proto  = (const float*)d_in[2];
    const float* ce_w1  = (const float*)d_in[3];
    const float* ce_b1  = (const float*)d_in[4];
    const float* ce_w2  = (const float*)d_in[5];
    const float* ce_b2  = (const float*)d_in[6];
    const float* rms_w  = (const float*)d_in[7];
    const float* nm_w1  = (const float*)d_in[8];
    const float* nm_b1  = (const float*)d_in[9];
    const float* nm_w2  = (const float*)d_in[10];
    const float* nm_b2  = (const float*)d_in[11];
    const float* ns_w1  = (const float*)d_in[12];
    const float* ns_b1  = (const float*)d_in[13];
    const float* ns_w2  = (const float*)d_in[14];
    const float* ns_b2  = (const float*)d_in[15];
    const float* sv_w1  = (const float*)d_in[16];
    const float* sv_b1  = (const float*)d_in[17];
    const float* sv_w2  = (const float*)d_in[18];
    const float* sv_b2  = (const float*)d_in[19];
    float* out = (float*)d_out;

    // zero atomic accumulators
    k_init<<<64, 1024>>>();

    // batch-invariant ctx chain
    k_ctx_mean<<<1, 256>>>(cb);
    k_gemv_atomic<<<8, 256>>>(ce_w1, /*vsel=*/0, /*osel=*/0, 256);   // h1pre
    k_epre<<<4, 256>>>(ce_w2, ce_b1);
    k_rms<<<1, 256>>>(ce_b2, rms_w);
    k_gemv_atomic<<<8, 256>>>(ns_w1, 1, 1, 256);                      // nsh
    k_gemv_atomic<<<8, 512>>>(nm_w1, 1, 2, 512);                      // base_c (wc rows 0..1023)
    k_gemv_atomic<<<8, 256>>>(sv_w1, 1, 3, 256);                      // sv ctx half
    k_norm_weights<<<1, 256>>>(ns_b1, ns_w2, ns_b2);

    // prototypes @ wp (independent of action)
    k_gemm<<<dim3(8, 8), 256>>>(proto, nm_w1 + (size_t)2048 * 512, /*asel=*/0, /*csel=*/0, 512);

    // the big one: action = mean over T of x
    k_reduce<<<dim3(64, 32), 256>>>(x);

    // action-dependent GEMMs
    k_gemm<<<dim3(8, 8), 256>>>(nullptr, nm_w1 + (size_t)1024 * 512, 1, 1, 512);  // act @ wa
    k_gemm<<<dim3(8, 4), 256>>>(nullptr, sv_w1 + (size_t)1024 * 256, 1, 2, 256);  // act @ sv_w1[1024:]

    // outputs
    k_conf<<<64, 256>>>(nm_b1, nm_w2, nm_b2, out);
    k_sev<<<64, 256>>>(sv_b1, sv_w2, sv_b2, out);
}

// round 3
// speedup vs baseline: 4.7789x; 4.7789x over previous
#include <cuda_runtime.h>
#include <math.h>

#define DD 1024
#define BB 64

// ---------------- device scratch (no allocations allowed) ----------------
__device__ float g_part[BB * 8 * DD];        // reduce slab partials (pre-scaled by 1/2048)
__device__ float g_basec[512];               // ctx_enc @ wc
__device__ float g_svctx[256];               // ctx_enc @ sv_w1[:1024]
__device__ float g_norm_w[64];               // softmax norm weights (batch-invariant)
__device__ float g_proto_part[2][64 * 512];  // proto @ wp, k-split 2
__device__ float g_act_part[8][64 * 512];    // action @ wa, k-split 8
__device__ float g_svh_part[8][64 * 256];    // action @ sv_w1[1024:], k-split 8

__device__ __forceinline__ float gelu_f(float x) {
    return 0.5f * x * (1.0f + erff(x * 0.70710678118654752440f));
}
__device__ __forceinline__ float sigmoid_f(float x) {
    return 1.0f / (1.0f + expf(-x));
}

// ---------------- register-tiled 64x64 GEMM slice -------------------------
// C_part[64 x 64cols@nt] = A[64 x (k0..k0+Kb)] @ W[k0.., nt*64..]
// Works with blockDim 256 (all active) or 1024 (tid<256 active; others only sync).
// A source: direct gmem (a_from_part=0) or sum of 8 g_part slabs (=1).
__device__ __forceinline__ void gemm64(const float* __restrict__ Ag, int a_from_part,
                                       const float* __restrict__ W, int N,
                                       int nt, int k0, int Kb,
                                       float* __restrict__ Cp, float* sm)
{
    float* As = sm;               // [64][33] padded
    float* Ws = sm + 64 * 33;     // [32][64]
    int tid = threadIdx.x;
    bool act = (tid < 256);
    int tx = tid & 15;            // 16 col groups x 4 cols
    int ty = (tid >> 4) & 15;     // 16 row groups x 4 rows
    float acc[4][4];
#pragma unroll
    for (int r = 0; r < 4; r++)
#pragma unroll
        for (int c = 0; c < 4; c++) acc[r][c] = 0.f;

    for (int kb = 0; kb < Kb; kb += 32) {
        int kbase = k0 + kb;
        if (act) {
            // stage A slice [64 rows][32 k], coalesced along k
            for (int e = tid; e < 64 * 32; e += 256) {
                int m = e >> 5, kk = e & 31;
                float a;
                if (a_from_part) {
                    a = 0.f;
#pragma unroll
                    for (int s = 0; s < 8; s++)
                        a += g_part[(size_t)(m * 8 + s) * DD + kbase + kk];
                } else {
                    a = Ag[(size_t)m * DD + kbase + kk];
                }
                As[m * 33 + kk] = a;
            }
            // stage W slice [32 k][64 cols], coalesced along n
            for (int e = tid; e < 32 * 64; e += 256) {
                int kk = e >> 6, n = e & 63;
                Ws[kk * 64 + n] = W[(size_t)(kbase + kk) * N + nt * 64 + n];
            }
        }
        __syncthreads();
        if (act) {
#pragma unroll
            for (int kk = 0; kk < 32; kk++) {
                float4 wf = *(const float4*)&Ws[kk * 64 + tx * 4];
                float a0 = As[(ty * 4 + 0) * 33 + kk];
                float a1 = As[(ty * 4 + 1) * 33 + kk];
                float a2 = As[(ty * 4 + 2) * 33 + kk];
                float a3 = As[(ty * 4 + 3) * 33 + kk];
                acc[0][0] += a0 * wf.x; acc[0][1] += a0 * wf.y; acc[0][2] += a0 * wf.z; acc[0][3] += a0 * wf.w;
                acc[1][0] += a1 * wf.x; acc[1][1] += a1 * wf.y; acc[1][2] += a1 * wf.z; acc[1][3] += a1 * wf.w;
                acc[2][0] += a2 * wf.x; acc[2][1] += a2 * wf.y; acc[2][2] += a2 * wf.z; acc[2][3] += a2 * wf.w;
                acc[3][0] += a3 * wf.x; acc[3][1] += a3 * wf.y; acc[3][2] += a3 * wf.z; acc[3][3] += a3 * wf.w;
            }
        }
        __syncthreads();
    }
    if (act) {
#pragma unroll
        for (int r = 0; r < 4; r++) {
            float4 v = make_float4(acc[r][0], acc[r][1], acc[r][2], acc[r][3]);
            *(float4*)&Cp[(size_t)(ty * 4 + r) * N + nt * 64 + tx * 4] = v;
        }
    }
}

// ---------------- k_main: chain(block0) + proto(1..16) + reduce(17..528) ----
__global__ __launch_bounds__(1024, 1)
void k_main(const float* __restrict__ x, const float* __restrict__ cb,
            const float* __restrict__ proto,
            const float* __restrict__ ce_w1, const float* __restrict__ ce_b1,
            const float* __restrict__ ce_w2, const float* __restrict__ ce_b2,
            const float* __restrict__ rms_w,
            const float* __restrict__ nm_w1,
            const float* __restrict__ ns_w1, const float* __restrict__ ns_b1,
            const float* __restrict__ ns_w2, const float* __restrict__ ns_b2,
            const float* __restrict__ sv_w1)
{
    __shared__ __align__(16) float sm[8448];
    int tid = threadIdx.x;
    int blk = blockIdx.x;

    if (blk == 0) {
        // ============== batch-invariant ctx chain, one block, 1024 threads ==
        float* sc   = sm;            // 1024: ctx, then ctx_enc
        float* sred = sm + 1024;     // 1024
        float* sh   = sm + 2048;     // 256
        float* slg  = sm + 2304;     // 64

        // ctx = mean over 16 rows of context buffer
        {
            float a = 0.f;
#pragma unroll
            for (int r = 0; r < 16; r++) a += cb[r * DD + tid];
            sc[tid] = a * (1.0f / 16.0f);
        }
        __syncthreads();

        // h1pre[j] = ctx @ ce_w1 ; split d into 4 chunks of 256
        {
            int j = tid & 255, c = tid >> 8;
            const float* cp = sc + c * 256;
            const float* Wp = ce_w1 + (size_t)(c * 256) * 256 + j;
            float a = 0.f;
#pragma unroll 16
            for (int i = 0; i < 256; i++) a += cp[i] * Wp[(size_t)i * 256];
            sred[tid] = a;
        }
        __syncthreads();
        if (tid < 256) {
            float v = sred[tid] + sred[256 + tid] + sred[512 + tid] + sred[768 + tid] + ce_b1[tid];
            sh[tid] = gelu_f(v);
        }
        __syncthreads();

        // epre[d] + rmsnorm
        float e;
        {
            const float* Wp = ce_w2 + tid;
            float a = 0.f;
#pragma unroll 16
            for (int j = 0; j < 256; j++) a += sh[j] * Wp[(size_t)j * DD];
            e = a + ce_b2[tid];
            sred[tid] = e * e;
        }
        __syncthreads();
        for (int s = 512; s > 0; s >>= 1) {
            if (tid < s) sred[tid] += sred[tid + s];
            __syncthreads();
        }
        {
            float inv = rsqrtf(sred[0] * (1.0f / 1024.0f) + 1e-6f);
            __syncthreads();
            sc[tid] = e * inv * rms_w[tid];   // ctx_enc
        }
        __syncthreads();

        // nsh[j] = ctx_enc @ ns_w1
        {
            int j = tid & 255, c = tid >> 8;
            const float* cp = sc + c * 256;
            const float* Wp = ns_w1 + (size_t)(c * 256) * 256 + j;
            float a = 0.f;
#pragma unroll 16
            for (int i = 0; i < 256; i++) a += cp[i] * Wp[(size_t)i * 256];
            sred[tid] = a;
        }
        __syncthreads();
        if (tid < 256) {
            float v = sred[tid] + sred[256 + tid] + sred[512 + tid] + sred[768 + tid] + ns_b1[tid];
            sh[tid] = gelu_f(v);
        }
        __syncthreads();

        // logits[k] = ts @ ns_w2 + b ; softmax -> g_norm_w
        {
            int k = tid & 63, c = tid >> 6;   // 16 chunks of 16 j
            const float* tp = sh + c * 16;
            const float* Wp = ns_w2 + (size_t)(c * 16) * 64 + k;
            float a = 0.f;
#pragma unroll
            for (int i = 0; i < 16; i++) a += tp[i] * Wp[(size_t)i * 64];
            sred[tid] = a;
        }
        __syncthreads();
        if (tid < 64) {
            float a = ns_b2[tid];
#pragma unroll
            for (int c = 0; c < 16; c++) a += sred[c * 64 + tid];
            slg[tid] = a;
        }
        __syncthreads();
        if (tid < 64) {
            float m = -1e30f;
            for (int k = 0; k < 64; k++) m = fmaxf(m, slg[k]);
            float s = 0.f;
            for (int k = 0; k < 64; k++) s += expf(slg[k] - m);
            g_norm_w[tid] = expf(slg[tid] - m) / s;
        }
        __syncthreads();

        // svctx[j] = ctx_enc @ sv_w1[:1024]
        {
            int j = tid & 255, c = tid >> 8;
            const float* cp = sc + c * 256;
            const float* Wp = sv_w1 + (size_t)(c * 256) * 256 + j;
            float a = 0.f;
#pragma unroll 16
            for (int i = 0; i < 256; i++) a += cp[i] * Wp[(size_t)i * 256];
            sred[tid] = a;
        }
        __syncthreads();
        if (tid < 256)
            g_svctx[tid] = sred[tid] + sred[256 + tid] + sred[512 + tid] + sred[768 + tid];
        __syncthreads();

        // basec[h] = ctx_enc @ wc (nm_w1 rows 0..1023), split d into 2x512
        {
            int h = tid & 511, c = tid >> 9;
            const float* cp = sc + c * 512;
            const float* Wp = nm_w1 + (size_t)(c * 512) * 512 + h;
            float a = 0.f;
#pragma unroll 16
            for (int i = 0; i < 512; i++) a += cp[i] * Wp[(size_t)i * 512];
            sred[tid] = a;
        }
        __syncthreads();
        if (tid < 512) g_basec[tid] = sred[tid] + sred[512 + tid];
    }
    else if (blk <= 16) {
        // ============== proto @ wp ; k-split 2, 8 n-tiles (shadowed) ========
        int pi = blk - 1;
        int nt = pi & 7, ks = pi >> 3;
        gemm64(proto, 0, nm_w1 + (size_t)2048 * 512, 512, nt, ks * 512, 512,
               g_proto_part[ks], sm);
    }
    else {
        // ============== big reduce: x mean partials ========================
        int i = blk - 17;
        int b = i >> 3, s = i & 7;
        int d4 = tid & 255, g = tid >> 8;
        const float4* xp = (const float4*)x
                         + ((size_t)b * 2048 + s * 256 + g * 64) * 256 + d4;
        float4 a = make_float4(0.f, 0.f, 0.f, 0.f);
#pragma unroll 8
        for (int t = 0; t < 64; t++) {
            float4 v = __ldcs(xp + (size_t)t * 256);
            a.x += v.x; a.y += v.y; a.z += v.z; a.w += v.w;
        }
        float4* sm4 = (float4*)sm;
        sm4[g * 256 + d4] = a;
        __syncthreads();
        if (g == 0) {
            float4 r0 = sm4[d4], r1 = sm4[256 + d4], r2 = sm4[512 + d4], r3 = sm4[768 + d4];
            const float sc = 1.0f / 2048.0f;
            float4 r;
            r.x = (r0.x + r1.x + r2.x + r3.x) * sc;
            r.y = (r0.y + r1.y + r2.y + r3.y) * sc;
            r.z = (r0.z + r1.z + r2.z + r3.z) * sc;
            r.w = (r0.w + r1.w + r2.w + r3.w) * sc;
            ((float4*)g_part)[(size_t)(b * 8 + s) * 256 + d4] = r;
        }
    }
}

// ---------------- k_tail: action GEMMs (wa N=512, sv N=256) ----------------
__global__ __launch_bounds__(256, 4)
void k_tail(const float* __restrict__ nm_w1, const float* __restrict__ sv_w1)
{
    __shared__ __align__(16) float sm[64 * 33 + 32 * 64];
    int blk = blockIdx.x;
    if (blk < 64) {                 // action @ wa : 8 nt x 8 ks
        int nt = blk & 7, ks = blk >> 3;
        gemm64(nullptr, 1, nm_w1 + (size_t)1024 * 512, 512, nt, ks * 128, 128,
               g_act_part[ks], sm);
    } else {                        // action @ sv_w1[1024:] : 4 nt x 8 ks
        int i = blk - 64;
        int nt = i & 3, ks = i >> 2;
        gemm64(nullptr, 1, sv_w1 + (size_t)1024 * 256, 256, nt, ks * 128, 128,
               g_svh_part[ks], sm);
    }
}

// ---------------- k_confsev: conformance + severity + outputs --------------
__global__ __launch_bounds__(256, 4)
void k_confsev(const float* __restrict__ nm_b1, const float* __restrict__ nm_w2,
               const float* __restrict__ nm_b2,
               const float* __restrict__ sv_b1, const float* __restrict__ sv_w2,
               const float* __restrict__ sv_b2,
               float* __restrict__ out)
{
    __shared__ float s[512], w2[512], conf[64], red[256];
    int b = blockIdx.x;
    int tid = threadIdx.x;

    for (int h = tid; h < 512; h += 256) {
        float a = g_basec[h] + nm_b1[h];
#pragma unroll
        for (int p = 0; p < 8; p++) a += g_act_part[p][b * 512 + h];
        s[h] = a;
        w2[h] = nm_w2[h];
    }
    __syncthreads();

    int warp = tid >> 5, lane = tid & 31;
    float bias2 = nm_b2[0];
    for (int kk = 0; kk < 8; kk++) {
        int k = warp * 8 + kk;
        const float* p0 = &g_proto_part[0][k * 512];
        const float* p1 = &g_proto_part[1][k * 512];
        float acc = 0.f;
        for (int h = lane; h < 512; h += 32)
            acc += gelu_f(s[h] + p0[h] + p1[h]) * w2[h];
        for (int o = 16; o > 0; o >>= 1)
            acc += __shfl_down_sync(0xffffffffu, acc, o);
        if (lane == 0) conf[k] = sigmoid_f(acc + bias2);
    }
    __syncthreads();

    // severity partials
    {
        float a = g_svctx[tid] + sv_b1[tid];
#pragma unroll
        for (int p = 0; p < 8; p++) a += g_svh_part[p][b * 256 + tid];
        red[tid] = gelu_f(a) * sv_w2[tid];
    }
    __syncthreads();
    for (int st = 128; st > 0; st >>= 1) {
        if (tid < st) red[tid] += red[tid + st];
        __syncthreads();
    }
    if (tid == 0) {
        float wc = 0.f;
#pragma unroll
        for (int k = 0; k < 64; k++) wc += conf[k] * g_norm_w[k];
        float viol = 1.0f - wc;
        float sev = sigmoid_f(red[0] + sv_b2[0]);
        out[64 + b]  = wc;
        out[128 + b] = viol;
        out[192 + b] = sev;
        out[b]       = viol * sev * 0.1f;
    }
}

extern "C" void kernel_launch(void* const* d_in, const int* in_sizes, int n_in,
                              void* d_out, int out_size) {
    const float* x      = (const float*)d_in[0];
    const float* cb     = (const float*)d_in[1];
    const float* proto  = (const float*)d_in[2];
    const float* ce_w1  = (const float*)d_in[3];
    const float* ce_b1  = (const float*)d_in[4];
    const float* ce_w2  = (const float*)d_in[5];
    const float* ce_b2  = (const float*)d_in[6];
    const float* rms_w  = (const float*)d_in[7];
    const float* nm_w1  = (const float*)d_in[8];
    const float* nm_b1  = (const float*)d_in[9];
    const float* nm_w2  = (const float*)d_in[10];
    const float* nm_b2  = (const float*)d_in[11];
    const float* ns_w1  = (const float*)d_in[12];
    const float* ns_b1  = (const float*)d_in[13];
    const float* ns_w2  = (const float*)d_in[14];
    const float* ns_b2  = (const float*)d_in[15];
    const float* sv_w1  = (const float*)d_in[16];
    const float* sv_b1  = (const float*)d_in[17];
    const float* sv_w2  = (const float*)d_in[18];
    const float* sv_b2  = (const float*)d_in[19];
    float* out = (float*)d_out;

    k_main<<<529, 1024>>>(x, cb, proto, ce_w1, ce_b1, ce_w2, ce_b2, rms_w,
                          nm_w1, ns_w1, ns_b1, ns_w2, ns_b2, sv_w1);
    k_tail<<<96, 256>>>(nm_w1, sv_w1);
    k_confsev<<<64, 256>>>(nm_b1, nm_w2, nm_b2, sv_b1, sv_w2, sv_b2, out);
}